// round 4
// baseline (speedup 1.0000x reference)
#include <cuda_runtime.h>
#include <math.h>
#include <stdint.h>

#define NN 50000
#define EE 800000
#define ET (EE + NN)
#define GG 32

// ---------------- scratch (device globals; no allocation allowed) ----------
__device__ float g_xl[NN * 256];
__device__ float g_xr[NN * 256];
__device__ float g_b1[NN * 256];
__device__ float g_b2[NN * 256];
__device__ int   g_deg[NN];
__device__ int   g_rowptr[NN + 1];
__device__ int   g_cursor[NN];
__device__ int   g_csrc[ET];
__device__ float g_sum[GG * 256];
__device__ float g_sq[GG * 256];
__device__ float g_cs[GG * 256];
__device__ float g_ct[GG * 256];
__device__ float g_cnt[GG];
__device__ float g_feat[GG * 16];

// ---------------- f32x2 packed helpers (Blackwell) --------------------------
__device__ __forceinline__ void ffma2(unsigned long long& d, unsigned long long a,
                                      unsigned long long b) {
    asm("fma.rn.f32x2 %0, %1, %2, %0;" : "+l"(d) : "l"(a), "l"(b));
}

// ---------------- CSR build -------------------------------------------------
__global__ void k_init_deg() {
    int i = blockIdx.x * blockDim.x + threadIdx.x;
    if (i < NN) g_deg[i] = 1;  // self loop
}

__global__ void k_count(const int* __restrict__ ei) {
    int e = blockIdx.x * blockDim.x + threadIdx.x;
    if (e < EE) atomicAdd(&g_deg[ei[EE + e]], 1);
}

// single-block warp-shuffle scan over NN elements
__global__ void k_scan() {
    __shared__ int warpsum[32];
    __shared__ int carry_s;
    const int tid = threadIdx.x, lane = tid & 31, w = tid >> 5;
    if (tid == 0) carry_s = 0;
    __syncthreads();
    for (int base = 0; base < NN; base += 1024) {
        int i = base + tid;
        int v = (i < NN) ? g_deg[i] : 0;
        // warp inclusive scan
        int s = v;
#pragma unroll
        for (int o = 1; o < 32; o <<= 1) {
            int t = __shfl_up_sync(0xffffffffu, s, o);
            if (lane >= o) s += t;
        }
        if (lane == 31) warpsum[w] = s;
        __syncthreads();
        if (w == 0) {
            int ws = warpsum[lane];
            int t2 = ws;
#pragma unroll
            for (int o = 1; o < 32; o <<= 1) {
                int t = __shfl_up_sync(0xffffffffu, t2, o);
                if (lane >= o) t2 += t;
            }
            warpsum[lane] = t2 - ws;  // exclusive
        }
        __syncthreads();
        int excl = carry_s + warpsum[w] + s - v;
        if (i < NN) {
            g_rowptr[i] = excl;
            g_cursor[i] = excl;
        }
        __syncthreads();
        if (tid == 1023) carry_s += warpsum[31] + s;  // warp31 excl-offset + its inclusive
        __syncthreads();
    }
    if (tid == 0) g_rowptr[NN] = carry_s;
}

__global__ void k_scatter(const int* __restrict__ ei) {
    int e = blockIdx.x * blockDim.x + threadIdx.x;
    if (e < ET) {
        int s, d;
        if (e < EE) { s = ei[e]; d = ei[EE + e]; }
        else        { s = d = e - EE; }
        int p = atomicAdd(&g_cursor[d], 1);
        g_csrc[p] = s;
    }
}

__global__ void k_count_batch(const int* __restrict__ batch) {
    int i = blockIdx.x * blockDim.x + threadIdx.x;
    if (i < NN) atomicAdd(&g_cnt[batch[i]], 1.0f);
}

// ---------------- GEMM C = A@B + bias (f32x2, dup-B, double-buffered) -------
// A [M,K] row-major, B [K,Nn] row-major. Tile 128x64, BK=16, 256 threads,
// per-thread 8 rows x 4 cols (rows packed in f32x2 pairs).
__global__ void __launch_bounds__(256)
k_gemm_bias(const float* __restrict__ A, const float* __restrict__ Bg,
            const float* __restrict__ bias, float* __restrict__ C,
            int M, int K, int Nn) {
    __shared__ float  As[2][16][132];   // padded: 2-way store conflicts, 16B-aligned rows
    __shared__ float2 Bs[2][16][64];    // duplicated pairs (b,b)
    const int tid = threadIdx.x;
    const int row0 = blockIdx.y * 128, col0 = blockIdx.x * 64;
    const int tr = tid >> 4;             // 0..15 -> rows tr*8..tr*8+7
    const int tc = tid & 15;             // cols tc*4..tc*4+3
    // A-load mapping: float4 index f -> row=f>>2, kc=(f&3)*4 (f = tid, tid+256)
    const int ar0 = tid >> 2, akc = (tid & 3) * 4;
    // B-load mapping: row=tid>>4, col4=(tid&15)*4
    const int br = tid >> 4, bc = (tid & 15) * 4;

    unsigned long long acc[4][4];
#pragma unroll
    for (int i = 0; i < 4; i++)
#pragma unroll
        for (int j = 0; j < 4; j++) acc[i][j] = 0ull;

    const int nkb = K >> 4;
    float4 a0, a1, b0;

    // prologue: load k-block 0
    a0 = (row0 + ar0 < M) ? *(const float4*)(A + (size_t)(row0 + ar0) * K + akc)
                          : make_float4(0.f, 0.f, 0.f, 0.f);
    a1 = (row0 + ar0 + 64 < M) ? *(const float4*)(A + (size_t)(row0 + ar0 + 64) * K + akc)
                               : make_float4(0.f, 0.f, 0.f, 0.f);
    b0 = *(const float4*)(Bg + (size_t)br * Nn + col0 + bc);
    {
        As[0][akc + 0][ar0] = a0.x; As[0][akc + 1][ar0] = a0.y;
        As[0][akc + 2][ar0] = a0.z; As[0][akc + 3][ar0] = a0.w;
        As[0][akc + 0][ar0 + 64] = a1.x; As[0][akc + 1][ar0 + 64] = a1.y;
        As[0][akc + 2][ar0 + 64] = a1.z; As[0][akc + 3][ar0 + 64] = a1.w;
        Bs[0][br][bc + 0] = make_float2(b0.x, b0.x);
        Bs[0][br][bc + 1] = make_float2(b0.y, b0.y);
        Bs[0][br][bc + 2] = make_float2(b0.z, b0.z);
        Bs[0][br][bc + 3] = make_float2(b0.w, b0.w);
    }
    __syncthreads();

    for (int kb = 0; kb < nkb; kb++) {
        const int cur = kb & 1;
        if (kb + 1 < nkb) {
            const int k0 = (kb + 1) << 4;
            a0 = (row0 + ar0 < M) ? *(const float4*)(A + (size_t)(row0 + ar0) * K + k0 + akc)
                                  : make_float4(0.f, 0.f, 0.f, 0.f);
            a1 = (row0 + ar0 + 64 < M) ? *(const float4*)(A + (size_t)(row0 + ar0 + 64) * K + k0 + akc)
                                       : make_float4(0.f, 0.f, 0.f, 0.f);
            b0 = *(const float4*)(Bg + (size_t)(k0 + br) * Nn + col0 + bc);
        }
#pragma unroll
        for (int kk = 0; kk < 16; kk++) {
            ulonglong2 ap01 = *(const ulonglong2*)&As[cur][kk][tr * 8];
            ulonglong2 ap23 = *(const ulonglong2*)&As[cur][kk][tr * 8 + 4];
            ulonglong2 bp01 = *(const ulonglong2*)&Bs[cur][kk][tc * 4];
            ulonglong2 bp23 = *(const ulonglong2*)&Bs[cur][kk][tc * 4 + 2];
            unsigned long long ap[4] = {ap01.x, ap01.y, ap23.x, ap23.y};
            unsigned long long bp[4] = {bp01.x, bp01.y, bp23.x, bp23.y};
#pragma unroll
            for (int i = 0; i < 4; i++)
#pragma unroll
                for (int j = 0; j < 4; j++) ffma2(acc[i][j], ap[i], bp[j]);
        }
        if (kb + 1 < nkb) {
            const int nxt = cur ^ 1;
            As[nxt][akc + 0][ar0] = a0.x; As[nxt][akc + 1][ar0] = a0.y;
            As[nxt][akc + 2][ar0] = a0.z; As[nxt][akc + 3][ar0] = a0.w;
            As[nxt][akc + 0][ar0 + 64] = a1.x; As[nxt][akc + 1][ar0 + 64] = a1.y;
            As[nxt][akc + 2][ar0 + 64] = a1.z; As[nxt][akc + 3][ar0 + 64] = a1.w;
            Bs[nxt][br][bc + 0] = make_float2(b0.x, b0.x);
            Bs[nxt][br][bc + 1] = make_float2(b0.y, b0.y);
            Bs[nxt][br][bc + 2] = make_float2(b0.z, b0.z);
            Bs[nxt][br][bc + 3] = make_float2(b0.w, b0.w);
            __syncthreads();
        }
    }

    float4 bs = *(const float4*)&bias[col0 + tc * 4];
#pragma unroll
    for (int i2 = 0; i2 < 4; i2++) {
        int r0 = row0 + tr * 8 + i2 * 2;
        float2 v0 = *(float2*)&acc[i2][0];
        float2 v1 = *(float2*)&acc[i2][1];
        float2 v2 = *(float2*)&acc[i2][2];
        float2 v3 = *(float2*)&acc[i2][3];
        if (r0 < M) {
            float4 o = make_float4(v0.x + bs.x, v1.x + bs.y, v2.x + bs.z, v3.x + bs.w);
            *(float4*)(C + (size_t)r0 * Nn + col0 + tc * 4) = o;
        }
        if (r0 + 1 < M) {
            float4 o = make_float4(v0.y + bs.x, v1.y + bs.y, v2.y + bs.z, v3.y + bs.w);
            *(float4*)(C + (size_t)(r0 + 1) * Nn + col0 + tc * 4) = o;
        }
    }
}

// ---------------- fused single-pass GATv2 attention (no-max softmax) --------
// exp without max subtraction: scores are O(5); result identical to reference's
// max-subtracted softmax up to fp rounding.
template <int D, bool CONCAT>
__global__ void k_attn(const float* __restrict__ xl, const float* __restrict__ xr,
                       const float* __restrict__ att, const float* __restrict__ bias,
                       float* __restrict__ out) {
    constexpr int HD = 4 * D;
    constexpr int NW = HD / 32;
    const int node = blockIdx.x;
    const int tid = threadIdx.x, lane = tid & 31, w = tid >> 5;
    __shared__ float sxr[HD], satt[HD];
    __shared__ float sden[NW][4];
    __shared__ float sacc[NW][HD];
    __shared__ float sinv[4];

    sxr[tid] = xr[(size_t)node * HD + tid];
    satt[tid] = att[tid];
    __syncthreads();

    const int beg = g_rowptr[node], end = g_rowptr[node + 1];

    float den[4] = {0.f, 0.f, 0.f, 0.f};
    float acc[NW];
#pragma unroll
    for (int k = 0; k < NW; k++) acc[k] = 0.f;

    for (int e = beg + w; e < end; e += NW) {
        const float* xs = xl + (size_t)g_csrc[e] * HD;
        float xv[NW];
        float ph[4] = {0.f, 0.f, 0.f, 0.f};
#pragma unroll
        for (int k = 0; k < NW; k++) {
            int c = lane + 32 * k;
            float xval = xs[c];
            xv[k] = xval;
            float m = xval + sxr[c];
            m = m > 0.f ? m : 0.2f * m;
            int h = (D == 64) ? (k >> 1) : (D == 32) ? k : ((k << 1) + (lane >> 4));
            ph[h] = fmaf(m, satt[c], ph[h]);
        }
#pragma unroll
        for (int o = 16; o; o >>= 1) {
#pragma unroll
            for (int h = 0; h < 4; h++)
                ph[h] += __shfl_xor_sync(0xffffffffu, ph[h], o);
        }
        float wg[4];
#pragma unroll
        for (int h = 0; h < 4; h++) {
            wg[h] = __expf(ph[h]);
            den[h] += wg[h];
        }
#pragma unroll
        for (int k = 0; k < NW; k++) {
            int h = (D == 64) ? (k >> 1) : (D == 32) ? k : ((k << 1) + (lane >> 4));
            acc[k] = fmaf(wg[h], xv[k], acc[k]);
        }
    }
#pragma unroll
    for (int k = 0; k < NW; k++) sacc[w][lane + 32 * k] = acc[k];
    if (lane < 4) sden[w][lane] = den[lane];
    __syncthreads();

    if (tid < 4) {
        float dt = 0.f;
#pragma unroll
        for (int i = 0; i < NW; i++) dt += sden[i][tid];
        sinv[tid] = 1.f / (dt + 1e-16f);
    }
    __syncthreads();

    {
        const int c = tid, h = c / D;
        float a = 0.f;
#pragma unroll
        for (int i = 0; i < NW; i++) a += sacc[i][c];
        float r = a * sinv[h];
        if (CONCAT) {
            out[(size_t)node * HD + c] = r + bias[c];
        } else {
            sxr[c] = r;  // reuse smem for head-average
        }
    }
    if (!CONCAT) {
        __syncthreads();
        if (tid < D)
            out[(size_t)node * D + tid] =
                0.25f * (sxr[tid] + sxr[D + tid] + sxr[2 * D + tid] + sxr[3 * D + tid]) + bias[tid];
    }
}

// ---------------- GraphNorm (one-pass sum/sumsq + coef + apply) --------------
#define GN_CHUNK 64
__global__ void k_gn_reduce(const float* __restrict__ x, const int* __restrict__ batch,
                            int F) {
    __shared__ int sb[GN_CHUNK];
    const int tid = threadIdx.x;
    const int R = 256 / F < 1 ? 1 : 256 / F;
    const int f = tid % F;
    const int r = tid / F;
    const int n0 = blockIdx.x * GN_CHUNK;
    if (tid < GN_CHUNK) sb[tid] = (n0 + tid < NN) ? batch[n0 + tid] : -1;
    __syncthreads();
    if (r >= R) return;
    float s = 0.f, q = 0.f;
    int cg = -1;
    for (int i = r; i < GN_CHUNK && n0 + i < NN; i += R) {
        int g = sb[i];
        if (g != cg) {
            if (cg >= 0) {
                atomicAdd(&g_sum[cg * F + f], s);
                atomicAdd(&g_sq[cg * F + f], q);
            }
            s = 0.f; q = 0.f; cg = g;
        }
        float v = x[(size_t)(n0 + i) * F + f];
        s += v;
        q = fmaf(v, v, q);
    }
    if (cg >= 0) {
        atomicAdd(&g_sum[cg * F + f], s);
        atomicAdd(&g_sq[cg * F + f], q);
    }
}

__global__ void k_gn_coef(const float* __restrict__ w, const float* __restrict__ b,
                          const float* __restrict__ a, int F) {
    int i = blockIdx.x * blockDim.x + threadIdx.x;
    if (i < GG * F) {
        int f = i % F;
        float c = fmaxf(g_cnt[i / F], 1.0f);
        float mean = g_sum[i] / c;
        float av = a[f];
        float var = g_sq[i] / c + mean * mean * (av * av - 2.f * av);
        var = fmaxf(var, 0.f);
        float s = w[f] * rsqrtf(var + 1e-5f);
        g_cs[i] = s;
        g_ct[i] = b[f] - s * av * mean;
    }
}

__global__ void k_gn_apply(float* __restrict__ x, const int* __restrict__ batch, int F) {
    int Fq = F >> 2;
    int idx = blockIdx.x * blockDim.x + threadIdx.x;
    if (idx < NN * Fq) {
        int n = idx / Fq, f4 = (idx - n * Fq) * 4;
        int g = batch[n];
        float4 xv = *(float4*)&x[(size_t)n * F + f4];
        float4 s = *(const float4*)&g_cs[g * F + f4];
        float4 t = *(const float4*)&g_ct[g * F + f4];
        float4 y;
        y.x = fmaxf(fmaf(s.x, xv.x, t.x), 0.f);
        y.y = fmaxf(fmaf(s.y, xv.y, t.y), 0.f);
        y.z = fmaxf(fmaf(s.z, xv.z, t.z), 0.f);
        y.w = fmaxf(fmaf(s.w, xv.w, t.w), 0.f);
        *(float4*)&x[(size_t)n * F + f4] = y;
    }
}

// ---------------- pooling + classifier head ---------------------------------
__global__ void k_pool(const float* __restrict__ h, const int* __restrict__ batch) {
    int idx = blockIdx.x * blockDim.x + threadIdx.x;
    if (idx < NN * 16) {
        int n = idx >> 4, f = idx & 15;
        atomicAdd(&g_feat[batch[n] * 16 + f], h[idx]);
    }
}

__global__ void k_head(const float* __restrict__ linW, const float* __restrict__ linB,
                       float* __restrict__ out) {
    __shared__ float sf[GG * 16];
    int tid = threadIdx.x;
    if (tid < GG * 16) {
        int g = tid / 16;
        float v = g_feat[tid] / fmaxf(g_cnt[g], 1.0f);
        sf[tid] = v;
        out[GG * 4 + tid] = v;  // features at offset 128
    }
    __syncthreads();
    if (tid < GG * 4) {
        int g = tid >> 2, c = tid & 3;
        float s = linB[c];
#pragma unroll
        for (int f = 0; f < 16; f++) s = fmaf(sf[g * 16 + f], linW[f * 4 + c], s);
        out[g * 4 + c] = s;  // logits at offset 0
    }
}

// ---------------- host orchestration ----------------------------------------
static void run_gemm(const float* A, const float* B, const float* bias, float* C,
                     int M, int K, int Nn) {
    dim3 grid(Nn / 64, (M + 127) / 128);
    k_gemm_bias<<<grid, 256>>>(A, B, bias, C, M, K, Nn);
}

static void run_graphnorm(float* x, const int* batch, const float* w, const float* bb,
                          const float* a, int F, float* sum, float* sq) {
    cudaMemsetAsync(sum, 0, (size_t)GG * F * sizeof(float));
    cudaMemsetAsync(sq, 0, (size_t)GG * F * sizeof(float));
    k_gn_reduce<<<(NN + GN_CHUNK - 1) / GN_CHUNK, 256>>>(x, batch, F);
    k_gn_coef<<<(GG * F + 255) / 256, 256>>>(w, bb, a, F);
    k_gn_apply<<<(NN * (F >> 2) + 255) / 256, 256>>>(x, batch, F);
}

extern "C" void kernel_launch(void* const* d_in, const int* in_sizes, int n_in,
                              void* d_out, int out_size) {
    const float* x     = (const float*)d_in[0];
    const int*   ei    = (const int*)d_in[1];
    const int*   batch = (const int*)d_in[2];
    const float* Wl1 = (const float*)d_in[3],  *bl1 = (const float*)d_in[4];
    const float* Wr1 = (const float*)d_in[5],  *br1 = (const float*)d_in[6];
    const float* att1 = (const float*)d_in[7], *bias1 = (const float*)d_in[8];
    const float* gw1 = (const float*)d_in[9],  *gb1 = (const float*)d_in[10], *ga1 = (const float*)d_in[11];
    const float* Wl2 = (const float*)d_in[12], *bl2 = (const float*)d_in[13];
    const float* Wr2 = (const float*)d_in[14], *br2 = (const float*)d_in[15];
    const float* att2 = (const float*)d_in[16], *bias2 = (const float*)d_in[17];
    const float* gw2 = (const float*)d_in[18], *gb2 = (const float*)d_in[19], *ga2 = (const float*)d_in[20];
    const float* Wl3 = (const float*)d_in[21], *bl3 = (const float*)d_in[22];
    const float* Wr3 = (const float*)d_in[23], *br3 = (const float*)d_in[24];
    const float* att3 = (const float*)d_in[25], *bias3 = (const float*)d_in[26];
    const float* gw3 = (const float*)d_in[27], *gb3 = (const float*)d_in[28], *ga3 = (const float*)d_in[29];
    const float* linW = (const float*)d_in[30], *linB = (const float*)d_in[31];

    float *xl, *xr, *b1, *b2, *sum, *sq, *cnt, *feat;
    cudaGetSymbolAddress((void**)&xl, g_xl);
    cudaGetSymbolAddress((void**)&xr, g_xr);
    cudaGetSymbolAddress((void**)&b1, g_b1);
    cudaGetSymbolAddress((void**)&b2, g_b2);
    cudaGetSymbolAddress((void**)&sum, g_sum);
    cudaGetSymbolAddress((void**)&sq, g_sq);
    cudaGetSymbolAddress((void**)&cnt, g_cnt);
    cudaGetSymbolAddress((void**)&feat, g_feat);

    // ---- CSR build (launches 0-3) ----
    k_init_deg<<<(NN + 255) / 256, 256>>>();
    k_count<<<(EE + 255) / 256, 256>>>(ei);
    k_scan<<<1, 1024>>>();
    k_scatter<<<(ET + 255) / 256, 256>>>(ei);

    // ---- layer 1 GEMMs (launches 4,5 — launch 5 is what ncu -s 5 -c 1 captures) ----
    run_gemm(x, Wl1, bl1, xl, NN, 128, 256);
    run_gemm(x, Wr1, br1, xr, NN, 128, 256);

    cudaMemsetAsync(cnt, 0, GG * sizeof(float));
    k_count_batch<<<(NN + 255) / 256, 256>>>(batch);

    // ---- layer 1: attention + GN ----
    k_attn<64, true><<<NN, 256>>>(xl, xr, att1, bias1, b1);
    run_graphnorm(b1, batch, gw1, gb1, ga1, 256, sum, sq);

    // ---- layer 2: 256 -> 4x32 concat (128) ----
    run_gemm(b1, Wl2, bl2, xl, NN, 256, 128);
    run_gemm(b1, Wr2, br2, xr, NN, 256, 128);
    k_attn<32, true><<<NN, 128>>>(xl, xr, att2, bias2, b2);
    run_graphnorm(b2, batch, gw2, gb2, ga2, 128, sum, sq);

    // ---- layer 3: 128 -> 4x16 averaged (16) ----
    run_gemm(b2, Wl3, bl3, xl, NN, 128, 64);
    run_gemm(b2, Wr3, br3, xr, NN, 128, 64);
    k_attn<16, false><<<NN, 64>>>(xl, xr, att3, bias3, b1);
    run_graphnorm(b1, batch, gw3, gb3, ga3, 16, sum, sq);

    // ---- global mean pool + linear head ----
    cudaMemsetAsync(feat, 0, GG * 16 * sizeof(float));
    k_pool<<<(NN * 16 + 255) / 256, 256>>>(b1, batch);
    k_head<<<1, 512>>>(linW, linB, (float*)d_out);
}

// round 5
// speedup vs baseline: 1.3386x; 1.3386x over previous
#include <cuda_runtime.h>
#include <cuda_fp16.h>
#include <math.h>
#include <stdint.h>

#define NN 50000
#define EE 800000
#define ET (EE + NN)
#define GG 32

// ---------------- scratch (device globals; no allocation allowed) ----------
__device__ float g_xl[NN * 256];
__device__ float g_xr[NN * 256];
__device__ float g_b1[NN * 256];
__device__ float g_b2[NN * 256];
__device__ int   g_deg[NN];
__device__ int   g_rowptr[NN + 1];
__device__ int   g_cursor[NN];
__device__ int   g_csrc[ET];
__device__ float g_sum[GG * 256];
__device__ float g_sq[GG * 256];
__device__ float g_cs[GG * 256];
__device__ float g_ct[GG * 256];
__device__ float g_cnt[GG];
__device__ float g_feat[GG * 16];

// ---------------- CSR build -------------------------------------------------
__global__ void k_init_deg() {
    int i = blockIdx.x * blockDim.x + threadIdx.x;
    if (i < NN) g_deg[i] = 1;  // self loop
}

__global__ void k_count(const int* __restrict__ ei) {
    int e = blockIdx.x * blockDim.x + threadIdx.x;
    if (e < EE) atomicAdd(&g_deg[ei[EE + e]], 1);
}

// single-block warp-shuffle scan over NN elements
__global__ void k_scan() {
    __shared__ int warpsum[32];
    __shared__ int carry_s;
    const int tid = threadIdx.x, lane = tid & 31, w = tid >> 5;
    if (tid == 0) carry_s = 0;
    __syncthreads();
    for (int base = 0; base < NN; base += 1024) {
        int i = base + tid;
        int v = (i < NN) ? g_deg[i] : 0;
        int s = v;
#pragma unroll
        for (int o = 1; o < 32; o <<= 1) {
            int t = __shfl_up_sync(0xffffffffu, s, o);
            if (lane >= o) s += t;
        }
        if (lane == 31) warpsum[w] = s;
        __syncthreads();
        if (w == 0) {
            int ws = warpsum[lane];
            int t2 = ws;
#pragma unroll
            for (int o = 1; o < 32; o <<= 1) {
                int t = __shfl_up_sync(0xffffffffu, t2, o);
                if (lane >= o) t2 += t;
            }
            warpsum[lane] = t2 - ws;  // exclusive
        }
        __syncthreads();
        int excl = carry_s + warpsum[w] + s - v;
        if (i < NN) {
            g_rowptr[i] = excl;
            g_cursor[i] = excl;
        }
        __syncthreads();
        if (tid == 1023) carry_s += warpsum[31] + s;
        __syncthreads();
    }
    if (tid == 0) g_rowptr[NN] = carry_s;
}

__global__ void k_scatter(const int* __restrict__ ei) {
    int e = blockIdx.x * blockDim.x + threadIdx.x;
    if (e < ET) {
        int s, d;
        if (e < EE) { s = ei[e]; d = ei[EE + e]; }
        else        { s = d = e - EE; }
        int p = atomicAdd(&g_cursor[d], 1);
        g_csrc[p] = s;
    }
}

__global__ void k_count_batch(const int* __restrict__ batch) {
    int i = blockIdx.x * blockDim.x + threadIdx.x;
    if (i < NN) atomicAdd(&g_cnt[batch[i]], 1.0f);
}

// ---------------- HMMA fp16-3x GEMM: C = A@B + bias --------------------------
// fp32 emulated via fp16 split: A=Ah+Al, B=Bh+Bl; C ~= Ah*Bh + Ah*Bl + Al*Bh.
// Dropped Al*Bl term is O(2^-22) relative. mma.sync m16n8k16, fp32 accum.
// Block: 256 thr (8 warps, 4Mx2N), tile 128x64, K-chunk 16.
// Fused dual-GEMM: blockIdx.z picks (B0,bias0,C0) or (B1,bias1,C1), same A.
__device__ __forceinline__ void mma16816(float* c, const uint32_t* a, const uint32_t* b) {
    asm volatile(
        "mma.sync.aligned.m16n8k16.row.col.f32.f16.f16.f32 "
        "{%0,%1,%2,%3}, {%4,%5,%6,%7}, {%8,%9}, {%0,%1,%2,%3};"
        : "+f"(c[0]), "+f"(c[1]), "+f"(c[2]), "+f"(c[3])
        : "r"(a[0]), "r"(a[1]), "r"(a[2]), "r"(a[3]), "r"(b[0]), "r"(b[1]));
}

#define APAD 20  // padded row stride (halves) for conflict-reduced frag loads

__global__ void __launch_bounds__(256)
k_gemm_mma(const float* __restrict__ A,
           const float* __restrict__ B0, const float* __restrict__ B1,
           const float* __restrict__ bias0, const float* __restrict__ bias1,
           float* __restrict__ C0, float* __restrict__ C1,
           int M, int K, int Nn) {
    const float* Bg   = blockIdx.z ? B1 : B0;
    const float* bias = blockIdx.z ? bias1 : bias0;
    float*       C    = blockIdx.z ? C1 : C0;

    __shared__ __half Ah[128 * APAD], Al[128 * APAD];
    __shared__ __half Bh[64 * APAD],  Bl[64 * APAD];

    const int tid = threadIdx.x, lane = tid & 31, wid = tid >> 5;
    const int row0 = blockIdx.y * 128, col0 = blockIdx.x * 64;
    const int wm = wid >> 1, wn = wid & 1;
    const int fr = lane >> 2, fc = (lane & 3) * 2;

    // loader mappings
    const int ar = tid >> 1, akq = (tid & 1) * 8;    // A: row ar, 8 floats at k=akq
    const int bk = tid >> 4, bn4 = (tid & 15) * 4;   // B: k-row bk, 4 cols at bn4

    float acc[2][4][4];
#pragma unroll
    for (int i = 0; i < 2; i++)
#pragma unroll
        for (int j = 0; j < 4; j++)
#pragma unroll
            for (int q = 0; q < 4; q++) acc[i][j][q] = 0.f;

    const int nkc = K >> 4;
    for (int kc = 0; kc < nkc; kc++) {
        // global loads
        float4 v0, v1;
        const float* Ap = A + (size_t)(row0 + ar) * K + kc * 16 + akq;
        if (row0 + ar < M) { v0 = *(const float4*)Ap; v1 = *(const float4*)(Ap + 4); }
        else { v0 = make_float4(0.f, 0.f, 0.f, 0.f); v1 = v0; }
        float4 wv = *(const float4*)(Bg + (size_t)(kc * 16 + bk) * Nn + col0 + bn4);

        __syncthreads();  // previous chunk's frag reads done

        // A hi/lo -> smem [m][k]
        {
            float av[8] = {v0.x, v0.y, v0.z, v0.w, v1.x, v1.y, v1.z, v1.w};
            int base = ar * APAD + akq;
#pragma unroll
            for (int j = 0; j < 8; j += 2) {
                __half h0 = __float2half_rn(av[j]), h1 = __float2half_rn(av[j + 1]);
                __half l0 = __float2half_rn(av[j] - __half2float(h0));
                __half l1 = __float2half_rn(av[j + 1] - __half2float(h1));
                *(__half2*)&Ah[base + j] = __halves2half2(h0, h1);
                *(__half2*)&Al[base + j] = __halves2half2(l0, l1);
            }
        }
        // B hi/lo -> smem transposed [n][k]
        {
            float bv[4] = {wv.x, wv.y, wv.z, wv.w};
#pragma unroll
            for (int j = 0; j < 4; j++) {
                __half h = __float2half_rn(bv[j]);
                __half l = __float2half_rn(bv[j] - __half2float(h));
                Bh[(bn4 + j) * APAD + bk] = h;
                Bl[(bn4 + j) * APAD + bk] = l;
            }
        }
        __syncthreads();

        // fragments
        uint32_t ah[2][4], al[2][4], bh[4][2], bl[4][2];
#pragma unroll
        for (int ma = 0; ma < 2; ma++) {
            int r = wm * 32 + ma * 16 + fr;
            ah[ma][0] = *(const uint32_t*)&Ah[r * APAD + fc];
            ah[ma][1] = *(const uint32_t*)&Ah[(r + 8) * APAD + fc];
            ah[ma][2] = *(const uint32_t*)&Ah[r * APAD + fc + 8];
            ah[ma][3] = *(const uint32_t*)&Ah[(r + 8) * APAD + fc + 8];
            al[ma][0] = *(const uint32_t*)&Al[r * APAD + fc];
            al[ma][1] = *(const uint32_t*)&Al[(r + 8) * APAD + fc];
            al[ma][2] = *(const uint32_t*)&Al[r * APAD + fc + 8];
            al[ma][3] = *(const uint32_t*)&Al[(r + 8) * APAD + fc + 8];
        }
#pragma unroll
        for (int na = 0; na < 4; na++) {
            int cn = wn * 32 + na * 8 + fr;
            bh[na][0] = *(const uint32_t*)&Bh[cn * APAD + fc];
            bh[na][1] = *(const uint32_t*)&Bh[cn * APAD + fc + 8];
            bl[na][0] = *(const uint32_t*)&Bl[cn * APAD + fc];
            bl[na][1] = *(const uint32_t*)&Bl[cn * APAD + fc + 8];
        }
#pragma unroll
        for (int ma = 0; ma < 2; ma++)
#pragma unroll
            for (int na = 0; na < 4; na++) {
                mma16816(acc[ma][na], ah[ma], bh[na]);
                mma16816(acc[ma][na], ah[ma], bl[na]);
                mma16816(acc[ma][na], al[ma], bh[na]);
            }
    }

    // epilogue + bias
#pragma unroll
    for (int ma = 0; ma < 2; ma++)
#pragma unroll
        for (int na = 0; na < 4; na++) {
            int r = row0 + wm * 32 + ma * 16 + fr;
            int c = col0 + wn * 32 + na * 8 + fc;
            float2 bb = *(const float2*)&bias[c];
            if (r < M)
                *(float2*)&C[(size_t)r * Nn + c] =
                    make_float2(acc[ma][na][0] + bb.x, acc[ma][na][1] + bb.y);
            if (r + 8 < M)
                *(float2*)&C[(size_t)(r + 8) * Nn + c] =
                    make_float2(acc[ma][na][2] + bb.x, acc[ma][na][3] + bb.y);
        }
}

// ---------------- fused single-pass GATv2 attention (no-max softmax) --------
template <int D, bool CONCAT>
__global__ void k_attn(const float* __restrict__ xl, const float* __restrict__ xr,
                       const float* __restrict__ att, const float* __restrict__ bias,
                       float* __restrict__ out) {
    constexpr int HD = 4 * D;
    constexpr int NW = HD / 32;
    const int node = blockIdx.x;
    const int tid = threadIdx.x, lane = tid & 31, w = tid >> 5;
    __shared__ float sxr[HD], satt[HD];
    __shared__ float sden[NW][4];
    __shared__ float sacc[NW][HD];
    __shared__ float sinv[4];

    sxr[tid] = xr[(size_t)node * HD + tid];
    satt[tid] = att[tid];
    __syncthreads();

    const int beg = g_rowptr[node], end = g_rowptr[node + 1];

    float den[4] = {0.f, 0.f, 0.f, 0.f};
    float acc[NW];
#pragma unroll
    for (int k = 0; k < NW; k++) acc[k] = 0.f;

    for (int e = beg + w; e < end; e += NW) {
        const float* xs = xl + (size_t)g_csrc[e] * HD;
        float xv[NW];
        float ph[4] = {0.f, 0.f, 0.f, 0.f};
#pragma unroll
        for (int k = 0; k < NW; k++) {
            int c = lane + 32 * k;
            float xval = xs[c];
            xv[k] = xval;
            float m = xval + sxr[c];
            m = m > 0.f ? m : 0.2f * m;
            int h = (D == 64) ? (k >> 1) : (D == 32) ? k : ((k << 1) + (lane >> 4));
            ph[h] = fmaf(m, satt[c], ph[h]);
        }
#pragma unroll
        for (int o = 16; o; o >>= 1) {
#pragma unroll
            for (int h = 0; h < 4; h++)
                ph[h] += __shfl_xor_sync(0xffffffffu, ph[h], o);
        }
        float wg[4];
#pragma unroll
        for (int h = 0; h < 4; h++) {
            wg[h] = __expf(ph[h]);
            den[h] += wg[h];
        }
#pragma unroll
        for (int k = 0; k < NW; k++) {
            int h = (D == 64) ? (k >> 1) : (D == 32) ? k : ((k << 1) + (lane >> 4));
            acc[k] = fmaf(wg[h], xv[k], acc[k]);
        }
    }
#pragma unroll
    for (int k = 0; k < NW; k++) sacc[w][lane + 32 * k] = acc[k];
    if (lane < 4) sden[w][lane] = den[lane];
    __syncthreads();

    if (tid < 4) {
        float dt = 0.f;
#pragma unroll
        for (int i = 0; i < NW; i++) dt += sden[i][tid];
        sinv[tid] = 1.f / (dt + 1e-16f);
    }
    __syncthreads();

    {
        const int c = tid, h = c / D;
        float a = 0.f;
#pragma unroll
        for (int i = 0; i < NW; i++) a += sacc[i][c];
        float r = a * sinv[h];
        if (CONCAT) {
            out[(size_t)node * HD + c] = r + bias[c];
        } else {
            sxr[c] = r;
        }
    }
    if (!CONCAT) {
        __syncthreads();
        if (tid < D)
            out[(size_t)node * D + tid] =
                0.25f * (sxr[tid] + sxr[D + tid] + sxr[2 * D + tid] + sxr[3 * D + tid]) + bias[tid];
    }
}

// ---------------- GraphNorm (one-pass sum/sumsq + coef + apply) --------------
// NOTE: g_sum/g_sq are zero on entry (zero-init at load; k_gn_coef re-zeroes
// after consuming), so no memsets needed — keeps graph node count low.
#define GN_CHUNK 64
__global__ void k_gn_reduce(const float* __restrict__ x, const int* __restrict__ batch,
                            int F) {
    __shared__ int sb[GN_CHUNK];
    const int tid = threadIdx.x;
    const int R = 256 / F < 1 ? 1 : 256 / F;
    const int f = tid % F;
    const int r = tid / F;
    const int n0 = blockIdx.x * GN_CHUNK;
    if (tid < GN_CHUNK) sb[tid] = (n0 + tid < NN) ? batch[n0 + tid] : -1;
    __syncthreads();
    if (r >= R) return;
    float s = 0.f, q = 0.f;
    int cg = -1;
    for (int i = r; i < GN_CHUNK && n0 + i < NN; i += R) {
        int g = sb[i];
        if (g != cg) {
            if (cg >= 0) {
                atomicAdd(&g_sum[cg * F + f], s);
                atomicAdd(&g_sq[cg * F + f], q);
            }
            s = 0.f; q = 0.f; cg = g;
        }
        float v = x[(size_t)(n0 + i) * F + f];
        s += v;
        q = fmaf(v, v, q);
    }
    if (cg >= 0) {
        atomicAdd(&g_sum[cg * F + f], s);
        atomicAdd(&g_sq[cg * F + f], q);
    }
}

__global__ void k_gn_coef(const float* __restrict__ w, const float* __restrict__ b,
                          const float* __restrict__ a, int F) {
    int i = blockIdx.x * blockDim.x + threadIdx.x;
    if (i < GG * F) {
        int f = i % F;
        float c = fmaxf(g_cnt[i / F], 1.0f);
        float mean = g_sum[i] / c;
        float av = a[f];
        float var = g_sq[i] / c + mean * mean * (av * av - 2.f * av);
        var = fmaxf(var, 0.f);
        float s = w[f] * rsqrtf(var + 1e-5f);
        g_cs[i] = s;
        g_ct[i] = b[f] - s * av * mean;
        g_sum[i] = 0.f;  // re-zero for next use / next replay
        g_sq[i] = 0.f;
    }
}

__global__ void k_gn_apply(float* __restrict__ x, const int* __restrict__ batch, int F) {
    int Fq = F >> 2;
    int idx = blockIdx.x * blockDim.x + threadIdx.x;
    if (idx < NN * Fq) {
        int n = idx / Fq, f4 = (idx - n * Fq) * 4;
        int g = batch[n];
        float4 xv = *(float4*)&x[(size_t)n * F + f4];
        float4 s = *(const float4*)&g_cs[g * F + f4];
        float4 t = *(const float4*)&g_ct[g * F + f4];
        float4 y;
        y.x = fmaxf(fmaf(s.x, xv.x, t.x), 0.f);
        y.y = fmaxf(fmaf(s.y, xv.y, t.y), 0.f);
        y.z = fmaxf(fmaf(s.z, xv.z, t.z), 0.f);
        y.w = fmaxf(fmaf(s.w, xv.w, t.w), 0.f);
        *(float4*)&x[(size_t)n * F + f4] = y;
    }
}

// ---------------- pooling + classifier head ---------------------------------
__global__ void k_pool(const float* __restrict__ h, const int* __restrict__ batch) {
    int idx = blockIdx.x * blockDim.x + threadIdx.x;
    if (idx < NN * 16) {
        int n = idx >> 4, f = idx & 15;
        atomicAdd(&g_feat[batch[n] * 16 + f], h[idx]);
    }
}

__global__ void k_head(const float* __restrict__ linW, const float* __restrict__ linB,
                       float* __restrict__ out) {
    __shared__ float sf[GG * 16];
    int tid = threadIdx.x;
    if (tid < GG * 16) {
        int g = tid / 16;
        float v = g_feat[tid] / fmaxf(g_cnt[g], 1.0f);
        sf[tid] = v;
        out[GG * 4 + tid] = v;   // features at offset 128
        g_feat[tid] = 0.f;       // re-zero for next replay
    }
    if (tid < GG) g_cnt[tid] = 0.f;
    __syncthreads();
    if (tid < GG * 4) {
        int g = tid >> 2, c = tid & 3;
        float s = linB[c];
#pragma unroll
        for (int f = 0; f < 16; f++) s = fmaf(sf[g * 16 + f], linW[f * 4 + c], s);
        out[g * 4 + c] = s;      // logits at offset 0
    }
}

// ---------------- host orchestration ----------------------------------------
static void run_gemm2(const float* A, const float* B0, const float* B1,
                      const float* bias0, const float* bias1,
                      float* C0, float* C1, int M, int K, int Nn) {
    dim3 grid(Nn / 64, (M + 127) / 128, 2);
    k_gemm_mma<<<grid, 256>>>(A, B0, B1, bias0, bias1, C0, C1, M, K, Nn);
}

static void run_graphnorm(float* x, const int* batch, const float* w, const float* bb,
                          const float* a, int F) {
    k_gn_reduce<<<(NN + GN_CHUNK - 1) / GN_CHUNK, 256>>>(x, batch, F);
    k_gn_coef<<<(GG * F + 255) / 256, 256>>>(w, bb, a, F);
    k_gn_apply<<<(NN * (F >> 2) + 255) / 256, 256>>>(x, batch, F);
}

extern "C" void kernel_launch(void* const* d_in, const int* in_sizes, int n_in,
                              void* d_out, int out_size) {
    const float* x     = (const float*)d_in[0];
    const int*   ei    = (const int*)d_in[1];
    const int*   batch = (const int*)d_in[2];
    const float* Wl1 = (const float*)d_in[3],  *bl1 = (const float*)d_in[4];
    const float* Wr1 = (const float*)d_in[5],  *br1 = (const float*)d_in[6];
    const float* att1 = (const float*)d_in[7], *bias1 = (const float*)d_in[8];
    const float* gw1 = (const float*)d_in[9],  *gb1 = (const float*)d_in[10], *ga1 = (const float*)d_in[11];
    const float* Wl2 = (const float*)d_in[12], *bl2 = (const float*)d_in[13];
    const float* Wr2 = (const float*)d_in[14], *br2 = (const float*)d_in[15];
    const float* att2 = (const float*)d_in[16], *bias2 = (const float*)d_in[17];
    const float* gw2 = (const float*)d_in[18], *gb2 = (const float*)d_in[19], *ga2 = (const float*)d_in[20];
    const float* Wl3 = (const float*)d_in[21], *bl3 = (const float*)d_in[22];
    const float* Wr3 = (const float*)d_in[23], *br3 = (const float*)d_in[24];
    const float* att3 = (const float*)d_in[25], *bias3 = (const float*)d_in[26];
    const float* gw3 = (const float*)d_in[27], *gb3 = (const float*)d_in[28], *ga3 = (const float*)d_in[29];
    const float* linW = (const float*)d_in[30], *linB = (const float*)d_in[31];

    float *xl, *xr, *b1, *b2;
    cudaGetSymbolAddress((void**)&xl, g_xl);
    cudaGetSymbolAddress((void**)&xr, g_xr);
    cudaGetSymbolAddress((void**)&b1, g_b1);
    cudaGetSymbolAddress((void**)&b2, g_b2);

    // ---- CSR build ----
    k_init_deg<<<(NN + 255) / 256, 256>>>();
    k_count<<<(EE + 255) / 256, 256>>>(ei);
    k_scan<<<1, 1024>>>();
    k_scatter<<<(ET + 255) / 256, 256>>>(ei);
    k_count_batch<<<(NN + 255) / 256, 256>>>(batch);

    // ---- layer 1: 128 -> 4x64 concat (256) ----
    run_gemm2(x, Wl1, Wr1, bl1, br1, xl, xr, NN, 128, 256);
    k_attn<64, true><<<NN, 256>>>(xl, xr, att1, bias1, b1);
    run_graphnorm(b1, batch, gw1, gb1, ga1, 256);

    // ---- layer 2: 256 -> 4x32 concat (128) ----
    run_gemm2(b1, Wl2, Wr2, bl2, br2, xl, xr, NN, 256, 128);
    k_attn<32, true><<<NN, 128>>>(xl, xr, att2, bias2, b2);
    run_graphnorm(b2, batch, gw2, gb2, ga2, 128);

    // ---- layer 3: 128 -> 4x16 averaged (16) ----
    run_gemm2(b2, Wl3, Wr3, bl3, br3, xl, xr, NN, 128, 64);
    k_attn<16, false><<<NN, 64>>>(xl, xr, att3, bias3, b1);
    run_graphnorm(b1, batch, gw3, gb3, ga3, 16);

    // ---- global mean pool + linear head ----
    k_pool<<<(NN * 16 + 255) / 256, 256>>>(b1, batch);
    k_head<<<1, 512>>>(linW, linB, (float*)d_out);
}